// round 16
// baseline (speedup 1.0000x reference)
#include <cuda_runtime.h>
#include <cuda_fp16.h>
#include <math.h>
#include <string.h>

#define SEQ 4096
#define INP 457
#define EMB 2048
#define G4E 8192
#define G4I 1828
#define NCTA 148
#define DCTA 57
#define CROWS 52   // fp16 Whh rows cached in SMEM per encoder CTA (rows 52-55 in regs)

__device__ float g_gx[(size_t)SEQ * G4E];     // Wih@x + biases, per timestep
__device__ float g_wihT[(size_t)INP * G4E];   // enc_Wih transposed
__device__ __half g_whh_h[(size_t)G4E * EMB]; // enc_Whh in fp16
__device__ float g_weff[(size_t)G4I * INP];   // (dec_Wih+dec_Whh)@dec_Whr
__device__ float g_g0[G4I];                   // decoder step-0 gates
__device__ float g_h[EMB];                    // final encoder hidden fp32 (for dec_g0)
__device__ uint4 g_hhu[2][256];               // encoder hidden fp16, double-buffered (4KB each)
// Encoder packed flags: 4 flags (4B each) in the first 16B of each 128B line.
__device__ uint4 g_flag_enc4[37 * 8];         // 148 flags -> 37 groups
// Decoder data-as-flag chunks: 64B per CTA per parity.
// words 0..8 = h_raw floats, word 15 = tag.
__device__ uint4 g_pub_dec[2][DCTA][4];

__device__ __forceinline__ float sigf(float x) { return 1.0f / (1.0f + expf(-x)); }

__device__ __forceinline__ __half2 u2h2(unsigned u) {
  __half2 h; memcpy(&h, &u, 4); return h;
}

// Poll one packed group of 4 flags until all >= tgt.
__device__ __forceinline__ void poll4(const uint4* gp, unsigned tgt) {
  unsigned v0, v1, v2, v3;
  do {
    asm volatile("ld.global.cg.v4.u32 {%0,%1,%2,%3},[%4];"
                 : "=r"(v0), "=r"(v1), "=r"(v2), "=r"(v3) : "l"(gp) : "memory");
  } while (v0 < tgt || v1 < tgt || v2 < tgt || v3 < tgt);
}

// fp16 conversion of enc_Whh + flag/hidden init (fused, launch #0).
__global__ void conv_init_kernel(const float* __restrict__ whh) {
  size_t i = (size_t)blockIdx.x * blockDim.x + threadIdx.x;
  size_t i4 = i * 4;
  float4 v = *(const float4*)(whh + i4);
  __half2* dst = (__half2*)(g_whh_h + i4);
  dst[0] = __floats2half2_rn(v.x, v.y);
  dst[1] = __floats2half2_rn(v.z, v.w);
  unsigned* fe = (unsigned*)g_flag_enc4;
  if (i < 37u * 32u) fe[i] = 0u;
  unsigned* pd = (unsigned*)g_pub_dec;
  if (i < 2u * DCTA * 16u) pd[i] = 0u;
  if (i < 512u) ((uint4*)g_hhu)[i] = make_uint4(0u, 0u, 0u, 0u);  // h_0 = 0
}

// Transpose enc_Wih [8192][457] -> g_wihT [457][8192]
__global__ void tr_kernel(const float* __restrict__ in) {
  __shared__ float tile[32][33];
  int r0 = blockIdx.x * 32, c0 = blockIdx.y * 32;
  int x = threadIdx.x;
  for (int y = threadIdx.y; y < 32; y += 8) {
    int c = c0 + x;
    if (c < INP) tile[y][x] = in[(size_t)(r0 + y) * INP + c];
  }
  __syncthreads();
  for (int y = threadIdx.y; y < 32; y += 8) {
    int c = c0 + y;
    if (c < INP) g_wihT[(size_t)c * G4E + r0 + x] = tile[x][y];
  }
}

// Gx[t][r] = sum_k x[t][k]*Wih[r][k] + bih[r] + bhh[r]   (FMA-bound; unchanged)
__global__ void __launch_bounds__(256) gx_kernel(const float* __restrict__ x,
                                                 const float* __restrict__ bih,
                                                 const float* __restrict__ bhh) {
  __shared__ float xs[INP * 20];
  const int tid = threadIdx.x;
  const int rb = blockIdx.x * 256, tb = blockIdx.y * 16;
  for (int i = tid; i < 16 * INP; i += 256) {
    int tt = i / INP, k = i - tt * INP;
    xs[k * 20 + tt] = x[(size_t)(tb + tt) * INP + k];
  }
  __syncthreads();
  const int r = rb + tid;
  float acc[16];
#pragma unroll
  for (int j = 0; j < 16; j++) acc[j] = 0.0f;
  for (int k = 0; k < INP; k++) {
    float w = g_wihT[(size_t)k * G4E + r];
    const float4* xv = (const float4*)(xs + k * 20);
    float4 a = xv[0], b = xv[1], c = xv[2], d = xv[3];
    acc[0]  += w * a.x; acc[1]  += w * a.y; acc[2]  += w * a.z; acc[3]  += w * a.w;
    acc[4]  += w * b.x; acc[5]  += w * b.y; acc[6]  += w * b.z; acc[7]  += w * b.w;
    acc[8]  += w * c.x; acc[9]  += w * c.y; acc[10] += w * c.z; acc[11] += w * c.w;
    acc[12] += w * d.x; acc[13] += w * d.y; acc[14] += w * d.z; acc[15] += w * d.w;
  }
  float bsum = bih[r] + bhh[r];
#pragma unroll
  for (int j = 0; j < 16; j++) g_gx[(size_t)(tb + j) * G4E + r] = acc[j] + bsum;
}

// W_eff[r][j] = sum_m (dWih[r][m]+dWhh[r][m]) * dWhr[m][j]
// 512 threads, 1 col/thread, 8 rows/block -> 3 blocks/SM, one wave.
__global__ void __launch_bounds__(512) weff_kernel(const float* __restrict__ dwih,
                                                   const float* __restrict__ dwhh,
                                                   const float* __restrict__ whr) {
  __shared__ float wcs[8 * 128];
  const int tid = threadIdx.x;
  const int r0 = blockIdx.x * 8;
  float acc[8];
#pragma unroll
  for (int i = 0; i < 8; i++) acc[i] = 0.0f;

  for (int kb = 0; kb < EMB; kb += 128) {
    __syncthreads();
    for (int idx = tid; idx < 8 * 128; idx += 512) {
      int i = idx >> 7, kk = idx & 127;
      int row = r0 + i; if (row > G4I - 1) row = G4I - 1;
      size_t gidx = (size_t)row * EMB + kb + kk;
      wcs[idx] = dwih[gidx] + dwhh[gidx];
    }
    __syncthreads();
#pragma unroll 4
    for (int kk = 0; kk < 128; kk++) {
      float v = (tid < INP) ? __ldg(whr + (size_t)(kb + kk) * INP + tid) : 0.0f;
#pragma unroll
      for (int i = 0; i < 8; i++) acc[i] += wcs[i * 128 + kk] * v;
    }
  }
  if (tid < INP) {
#pragma unroll
    for (int i = 0; i < 8; i++) {
      int row = r0 + i;
      if (row < G4I) g_weff[(size_t)row * INP + tid] = acc[i];
    }
  }
}

// Persistent encoder (R13-proven, unchanged): fp16 weights (52 rows SMEM + 4 in
// regs), HFMA2 4-accumulator inner loop, fp16 h exchange, packed-flag barrier.
extern __shared__ __half esmh[];
__global__ void __launch_bounds__(256, 1) enc_kernel() {
  __shared__ float gsum[64];
  const int tid = threadIdx.x, wid = tid >> 5, lane = tid & 31, b = blockIdx.x;
  const int cnt   = (b < 124) ? 14 : 13;
  const int start = (b < 124) ? 14 * b : 1736 + 13 * (b - 124);
  const int nrows = 4 * cnt;
  __half* ws  = esmh;                       // CROWS * 2048 halfs
  __half* hs2 = esmh + (size_t)CROWS * EMB; // 2048 halfs (h staging)

  for (int idx = tid; idx < CROWS * EMB; idx += 256) {
    int i = idx >> 11, k = idx & 2047;
    int e = start + (i >> 2), q = i & 3;
    ws[idx] = g_whh_h[((size_t)(q << 11) + e) * EMB + k];
  }
  uint4 wreg[8];
  const int regrow = 48 + wid;
  const bool hasreg = (wid >= 4) && (regrow < nrows);
  if (hasreg) {
    int e = start + (regrow >> 2), q = regrow & 3;
    const uint4* wr = (const uint4*)(g_whh_h + ((size_t)(q << 11) + e) * EMB);
#pragma unroll
    for (int j = 0; j < 8; j++) wreg[j] = __ldcg(wr + lane + 32 * j);
  }
  __syncthreads();

  float c = 0.0f;
  float gx0 = 0.f, gx1 = 0.f, gx2 = 0.f, gx3 = 0.f;
  if (tid < cnt) {
    size_t base = start + tid;
    gx0 = __ldcg(&g_gx[base]);
    gx1 = __ldcg(&g_gx[base + 2048]);
    gx2 = __ldcg(&g_gx[base + 4096]);
    gx3 = __ldcg(&g_gx[base + 6144]);
  }

  for (int t = 0; t < SEQ; t++) {
    ((uint4*)hs2)[tid] = __ldcg(&((const uint4*)g_hhu)[(t & 1) * 256 + tid]);
    __syncthreads();

    float pf0 = 0.f, pf1 = 0.f, pf2 = 0.f, pf3 = 0.f;
    if (tid < cnt && t + 1 < SEQ) {
      size_t base = (size_t)(t + 1) * G4E + start + tid;
      pf0 = __ldcg(&g_gx[base]);
      pf1 = __ldcg(&g_gx[base + 2048]);
      pf2 = __ldcg(&g_gx[base + 4096]);
      pf3 = __ldcg(&g_gx[base + 6144]);
    }

    uint4 hreg[8];
    const uint4* h4 = (const uint4*)hs2;
#pragma unroll
    for (int j = 0; j < 8; j++) hreg[j] = h4[lane + 32 * j];

#pragma unroll 1
    for (int k = 0; k < 6; k++) {      // rows 0..47: all SMEM
      int i = wid + 8 * k;
      const uint4* wr = (const uint4*)(ws + (size_t)i * EMB);
      __half2 a0 = __floats2half2_rn(0.f, 0.f), a1 = a0, a2 = a0, a3 = a0;
#pragma unroll
      for (int j = 0; j < 8; j++) {
        uint4 w = wr[lane + 32 * j];
        a0 = __hfma2(u2h2(w.x), u2h2(hreg[j].x), a0);
        a1 = __hfma2(u2h2(w.y), u2h2(hreg[j].y), a1);
        a2 = __hfma2(u2h2(w.z), u2h2(hreg[j].z), a2);
        a3 = __hfma2(u2h2(w.w), u2h2(hreg[j].w), a3);
      }
      float2 f0 = __half22float2(a0), f1 = __half22float2(a1);
      float2 f2 = __half22float2(a2), f3 = __half22float2(a3);
      float sum = (f0.x + f0.y) + (f1.x + f1.y) + (f2.x + f2.y) + (f3.x + f3.y);
#pragma unroll
      for (int o = 16; o; o >>= 1) sum += __shfl_xor_sync(0xffffffffu, sum, o);
      if (lane == 0) gsum[i] = sum;
    }
    {  // rows 48..55: SMEM for wid<4, registers for wid>=4
      int i = 48 + wid;
      if (i < nrows) {
        __half2 a0 = __floats2half2_rn(0.f, 0.f), a1 = a0, a2 = a0, a3 = a0;
        if (wid < 4) {
          const uint4* wr = (const uint4*)(ws + (size_t)i * EMB);
#pragma unroll
          for (int j = 0; j < 8; j++) {
            uint4 w = wr[lane + 32 * j];
            a0 = __hfma2(u2h2(w.x), u2h2(hreg[j].x), a0);
            a1 = __hfma2(u2h2(w.y), u2h2(hreg[j].y), a1);
            a2 = __hfma2(u2h2(w.z), u2h2(hreg[j].z), a2);
            a3 = __hfma2(u2h2(w.w), u2h2(hreg[j].w), a3);
          }
        } else {
#pragma unroll
          for (int j = 0; j < 8; j++) {
            uint4 w = wreg[j];
            a0 = __hfma2(u2h2(w.x), u2h2(hreg[j].x), a0);
            a1 = __hfma2(u2h2(w.y), u2h2(hreg[j].y), a1);
            a2 = __hfma2(u2h2(w.z), u2h2(hreg[j].z), a2);
            a3 = __hfma2(u2h2(w.w), u2h2(hreg[j].w), a3);
          }
        }
        float2 f0 = __half22float2(a0), f1 = __half22float2(a1);
        float2 f2 = __half22float2(a2), f3 = __half22float2(a3);
        float sum = (f0.x + f0.y) + (f1.x + f1.y) + (f2.x + f2.y) + (f3.x + f3.y);
#pragma unroll
        for (int o = 16; o; o >>= 1) sum += __shfl_xor_sync(0xffffffffu, sum, o);
        if (lane == 0) gsum[i] = sum;
      }
    }
    __syncthreads();

    if (tid < cnt) {
      float gi = gsum[4 * tid + 0] + gx0;
      float gf = gsum[4 * tid + 1] + gx1;
      float gg = gsum[4 * tid + 2] + gx2;
      float go = gsum[4 * tid + 3] + gx3;
      c = sigf(gf) * c + sigf(gi) * tanhf(gg);
      float hnew = sigf(go) * tanhf(c);
      ((__half*)g_hhu)[((t + 1) & 1) * 2048 + start + tid] = __float2half_rn(hnew);
      if (t == SEQ - 1) g_h[start + tid] = hnew;
      __threadfence();
    }
    gx0 = pf0; gx1 = pf1; gx2 = pf2; gx3 = pf3;

    if (t + 1 < SEQ) {
      __syncwarp();
      if (tid == 0)
        ((volatile unsigned*)g_flag_enc4)[(b >> 2) * 32 + (b & 3)] = (unsigned)(t + 1);
      if (tid < 37) {
        poll4(g_flag_enc4 + tid * 8, (unsigned)(t + 1));
        __threadfence();
      }
      __syncthreads();
    }
  }
}

// g0[r] = dec_Wih[r] . h_enc + bih[r] + bhh[r]
__global__ void dec_g0_kernel(const float* __restrict__ dwih,
                              const float* __restrict__ bih,
                              const float* __restrict__ bhh) {
  int wid = threadIdx.x >> 5, lane = threadIdx.x & 31;
  int row = blockIdx.x * 8 + wid;
  if (row >= G4I) return;
  const float4* w = (const float4*)(dwih + (size_t)row * EMB);
  const float4* h = (const float4*)g_h;
  float sum = 0.0f;
  for (int k = lane; k < EMB / 4; k += 32) {
    float4 a = w[k], b = h[k];
    sum += a.x * b.x + a.y * b.y + a.z * b.z + a.w * b.w;
  }
#pragma unroll
  for (int o = 16; o; o >>= 1) sum += __shfl_xor_sync(0xffffffffu, sum, o);
  if (lane == 0) g_g0[row] = sum + bih[row] + bhh[row];
}

// Persistent decoder: 57 CTAs, fp32, data-as-flag h_raw exchange.
// Publish: 9 floats + tag in one 64B chunk (st.cg data, st.release tag).
// Consume: thread j spin-polls chunk j's tag (ld.acquire), copies data to hrs.
// pscr is 16B-aligned (the R14 bug was a misaligned uint4 read here).
__global__ void __launch_bounds__(256, 1) dec_kernel(const float* __restrict__ bih,
                                                     const float* __restrict__ bhh,
                                                     float* __restrict__ out) {
  float* ws   = (float*)esmh;        // 36*INP = 16452 floats
  float* hrs  = ws + 36 * INP;       // +457  -> 16909
  float* bs   = hrs + INP;           // +36   -> 16945
  float* gsum = bs + 36;             // +36   -> 16981
  float* pscr = gsum + 36 + 3;       // +3 pad -> 16984 (16B-aligned: 67936 bytes)
  const int tid = threadIdx.x, wid = tid >> 5, lane = tid & 31, b = blockIdx.x;
  const int cnt = (b == 56) ? 9 : 8;
  const int e0 = 8 * b;
  const int nrows = 4 * cnt;

  for (int idx = tid; idx < nrows * INP; idx += 256) {
    int l = idx / INP, k = idx - l * INP;
    int q = l & 3, el = l >> 2;
    ws[l * INP + k] = g_weff[(size_t)(q * INP + e0 + el) * INP + k];
  }
  if (tid < nrows) {
    int q = tid & 3, el = tid >> 2;
    bs[tid] = bih[q * INP + e0 + el] + bhh[q * INP + e0 + el];
  }
  __syncthreads();

  float c = 0.0f;
  for (int t = 0; t < SEQ; t++) {
    if (t > 0) {
      // Consume: spin on producer tid's tag, then copy its chunk into hrs.
      if (tid < DCTA) {
        const uint4* ch = &g_pub_dec[t & 1][tid][0];
        const unsigned* tagp = (const unsigned*)ch + 15;
        unsigned tg;
        do {
          asm volatile("ld.global.acquire.gpu.u32 %0,[%1];"
                       : "=r"(tg) : "l"(tagp) : "memory");
        } while (tg < (unsigned)t);
        uint4 a = __ldcg(ch);
        uint4 b2 = __ldcg(ch + 1);
        unsigned w8 = __ldcg((const unsigned*)(ch + 2));
        float* hd = hrs + 8 * tid;
        hd[0] = __uint_as_float(a.x);  hd[1] = __uint_as_float(a.y);
        hd[2] = __uint_as_float(a.z);  hd[3] = __uint_as_float(a.w);
        hd[4] = __uint_as_float(b2.x); hd[5] = __uint_as_float(b2.y);
        hd[6] = __uint_as_float(b2.z); hd[7] = __uint_as_float(b2.w);
        if (tid == 56) hd[8] = __uint_as_float(w8);
      }
      __syncthreads();
#pragma unroll 1
      for (int k8 = 0; k8 < 5; k8++) {
        int l = wid + 8 * k8;
        if (l >= nrows) break;  // warp-uniform
        const float* wr = ws + l * INP;
        float sum = 0.0f;
#pragma unroll 5
        for (int k = lane; k < INP; k += 32) sum += wr[k] * hrs[k];
#pragma unroll
        for (int o = 16; o; o >>= 1) sum += __shfl_xor_sync(0xffffffffu, sum, o);
        if (lane == 0) gsum[l] = sum;
      }
      __syncthreads();
    }
    if (tid < cnt) {
      int e = e0 + tid;
      float gi, gf, gg, go;
      if (t == 0) {
        gi = g_g0[e]; gf = g_g0[INP + e]; gg = g_g0[2 * INP + e]; go = g_g0[3 * INP + e];
      } else {
        gi = gsum[4 * tid + 0] + bs[4 * tid + 0];
        gf = gsum[4 * tid + 1] + bs[4 * tid + 1];
        gg = gsum[4 * tid + 2] + bs[4 * tid + 2];
        go = gsum[4 * tid + 3] + bs[4 * tid + 3];
      }
      c = sigf(gf) * c + sigf(gi) * tanhf(gg);
      out[(size_t)(SEQ - 1 - t) * INP + e] = c;
      pscr[tid] = sigf(go) * tanhf(c);
    }
    // Publish: warp 0 packs and one thread stores data + release tag.
    if (wid == 0) {
      __syncwarp();
      if (lane == 0 && t + 1 < SEQ) {
        uint4* dst = &g_pub_dec[(t + 1) & 1][b][0];
        __stcg(dst, ((const uint4*)pscr)[0]);
        __stcg(dst + 1, ((const uint4*)pscr)[1]);
        asm volatile("st.global.cg.u32 [%0], %1;"
                     :: "l"((unsigned*)(dst + 2)), "r"(__float_as_uint(pscr[8]))
                     : "memory");
        asm volatile("st.global.release.gpu.u32 [%0], %1;"
                     :: "l"((unsigned*)dst + 15), "r"((unsigned)(t + 1))
                     : "memory");
      }
    }
  }
}

// In-place row softmax over out[4096][457]
__global__ void softmax_kernel(float* __restrict__ out) {
  __shared__ float red[32];
  const int t = blockIdx.x, tid = threadIdx.x, lane = tid & 31, wid = tid >> 5;
  float v = (tid < INP) ? out[(size_t)t * INP + tid] : -1e30f;
  float m = v;
#pragma unroll
  for (int o = 16; o; o >>= 1) m = fmaxf(m, __shfl_xor_sync(0xffffffffu, m, o));
  if (lane == 0) red[wid] = m;
  __syncthreads();
  m = -1e30f;
  for (int i = 0; i < 16; i++) m = fmaxf(m, red[i]);
  __syncthreads();
  float e = (tid < INP) ? expf(v - m) : 0.0f;
  float sum = e;
#pragma unroll
  for (int o = 16; o; o >>= 1) sum += __shfl_xor_sync(0xffffffffu, sum, o);
  if (lane == 0) red[wid] = sum;
  __syncthreads();
  sum = 0.0f;
  for (int i = 0; i < 16; i++) sum += red[i];
  if (tid < INP) out[(size_t)t * INP + tid] = e / sum;
}

extern "C" void kernel_launch(void* const* d_in, const int* in_sizes, int n_in,
                              void* d_out, int out_size) {
  const float* x    = (const float*)d_in[0];
  const float* eWih = (const float*)d_in[1];
  const float* eWhh = (const float*)d_in[2];
  const float* ebih = (const float*)d_in[3];
  const float* ebhh = (const float*)d_in[4];
  const float* dWih = (const float*)d_in[5];
  const float* dWhh = (const float*)d_in[6];
  const float* dbih = (const float*)d_in[7];
  const float* dbhh = (const float*)d_in[8];
  const float* dWhr = (const float*)d_in[9];
  float* out = (float*)d_out;

  const int enc_smem = (CROWS * EMB + EMB) * 2;                         // 217,088 B
  const int dec_smem = (36 * INP + INP + 36 + 36 + 3 + 12) * 4 + 64;    // ~68 KB
  cudaFuncSetAttribute(enc_kernel, cudaFuncAttributeMaxDynamicSharedMemorySize, enc_smem);
  cudaFuncSetAttribute(dec_kernel, cudaFuncAttributeMaxDynamicSharedMemorySize, dec_smem);

  conv_init_kernel<<<16384, 256>>>(eWhh);
  tr_kernel<<<dim3(256, 15), dim3(32, 8)>>>(eWih);
  gx_kernel<<<dim3(32, 256), 256>>>(x, ebih, ebhh);
  enc_kernel<<<NCTA, 256, enc_smem>>>();
  weff_kernel<<<229, 512>>>(dWih, dWhh, dWhr);
  dec_g0_kernel<<<229, 256>>>(dWih, dbih, dbhh);
  dec_kernel<<<DCTA, 256, dec_smem>>>(dbih, dbhh, out);
  softmax_kernel<<<SEQ, 512>>>(out);
}

// round 17
// speedup vs baseline: 1.1957x; 1.1957x over previous
#include <cuda_runtime.h>
#include <cuda_fp16.h>
#include <math.h>
#include <string.h>

#define SEQ 4096
#define INP 457
#define EMB 2048
#define G4E 8192
#define G4I 1828
#define NCTA 148
#define DCTA 57
#define CROWS 52   // fp16 Whh rows cached in SMEM per encoder CTA (rows 52-55 in regs)

__device__ float g_gx[(size_t)SEQ * G4E];     // Wih@x + biases, per timestep
__device__ float g_wihT[(size_t)INP * G4E];   // enc_Wih transposed
__device__ __half g_whh_h[(size_t)G4E * EMB]; // enc_Whh in fp16
__device__ float g_weff[(size_t)G4I * INP];   // (dec_Wih+dec_Whh)@dec_Whr
__device__ float g_g0[G4I];                   // decoder step-0 gates
__device__ float g_h[EMB];                    // final encoder hidden fp32 (for dec_g0)
__device__ uint4 g_hhu[2][256];               // encoder hidden fp16, double-buffered (4KB each)
__device__ float g_hraw[2 * INP];             // decoder raw hidden fp32, double-buffered
// Packed flags: 4 flags (4B each) in the first 16B of each 128B line.
__device__ uint4 g_flag_enc4[37 * 8];         // 148 flags -> 37 groups
__device__ uint4 g_flag_dec4[15 * 8];         // 57 flags  -> 15 groups (3 pad slots)

__device__ __forceinline__ float sigf(float x) { return 1.0f / (1.0f + expf(-x)); }

__device__ __forceinline__ __half2 u2h2(unsigned u) {
  __half2 h; memcpy(&h, &u, 4); return h;
}

// Poll one packed group of 4 flags until all >= tgt.
__device__ __forceinline__ void poll4(const uint4* gp, unsigned tgt) {
  unsigned v0, v1, v2, v3;
  do {
    asm volatile("ld.global.cg.v4.u32 {%0,%1,%2,%3},[%4];"
                 : "=r"(v0), "=r"(v1), "=r"(v2), "=r"(v3) : "l"(gp) : "memory");
  } while (v0 < tgt || v1 < tgt || v2 < tgt || v3 < tgt);
}

// fp16 conversion of enc_Whh + flag/hidden init (fused, launch #0).
__global__ void conv_init_kernel(const float* __restrict__ whh) {
  size_t i = (size_t)blockIdx.x * blockDim.x + threadIdx.x;
  size_t i4 = i * 4;
  float4 v = *(const float4*)(whh + i4);
  __half2* dst = (__half2*)(g_whh_h + i4);
  dst[0] = __floats2half2_rn(v.x, v.y);
  dst[1] = __floats2half2_rn(v.z, v.w);
  unsigned* fe = (unsigned*)g_flag_enc4;
  unsigned* fd = (unsigned*)g_flag_dec4;
  if (i < 37u * 32u) fe[i] = 0u;
  if (i < 15u * 32u) {
    // group 14 words 1..3 are padding: make them always-passing
    fd[i] = (i > 14u * 32u && i < 14u * 32u + 4u) ? 0x7FFFFFFFu : 0u;
  }
  if (i < 512u) ((uint4*)g_hhu)[i] = make_uint4(0u, 0u, 0u, 0u);  // h_0 = 0
}

// Transpose enc_Wih [8192][457] -> g_wihT [457][8192]
__global__ void tr_kernel(const float* __restrict__ in) {
  __shared__ float tile[32][33];
  int r0 = blockIdx.x * 32, c0 = blockIdx.y * 32;
  int x = threadIdx.x;
  for (int y = threadIdx.y; y < 32; y += 8) {
    int c = c0 + x;
    if (c < INP) tile[y][x] = in[(size_t)(r0 + y) * INP + c];
  }
  __syncthreads();
  for (int y = threadIdx.y; y < 32; y += 8) {
    int c = c0 + y;
    if (c < INP) g_wihT[(size_t)c * G4E + r0 + x] = tile[x][y];
  }
}

// Gx[t][r] = sum_k x[t][k]*Wih[r][k] + bih[r] + bhh[r]   (FMA-bound)
__global__ void __launch_bounds__(256) gx_kernel(const float* __restrict__ x,
                                                 const float* __restrict__ bih,
                                                 const float* __restrict__ bhh) {
  __shared__ float xs[INP * 20];
  const int tid = threadIdx.x;
  const int rb = blockIdx.x * 256, tb = blockIdx.y * 16;
  for (int i = tid; i < 16 * INP; i += 256) {
    int tt = i / INP, k = i - tt * INP;
    xs[k * 20 + tt] = x[(size_t)(tb + tt) * INP + k];
  }
  __syncthreads();
  const int r = rb + tid;
  float acc[16];
#pragma unroll
  for (int j = 0; j < 16; j++) acc[j] = 0.0f;
  for (int k = 0; k < INP; k++) {
    float w = g_wihT[(size_t)k * G4E + r];
    const float4* xv = (const float4*)(xs + k * 20);
    float4 a = xv[0], b = xv[1], c = xv[2], d = xv[3];
    acc[0]  += w * a.x; acc[1]  += w * a.y; acc[2]  += w * a.z; acc[3]  += w * a.w;
    acc[4]  += w * b.x; acc[5]  += w * b.y; acc[6]  += w * b.z; acc[7]  += w * b.w;
    acc[8]  += w * c.x; acc[9]  += w * c.y; acc[10] += w * c.z; acc[11] += w * c.w;
    acc[12] += w * d.x; acc[13] += w * d.y; acc[14] += w * d.z; acc[15] += w * d.w;
  }
  float bsum = bih[r] + bhh[r];
#pragma unroll
  for (int j = 0; j < 16; j++) g_gx[(size_t)(tb + j) * G4E + r] = acc[j] + bsum;
}

// W_eff[r][j] = sum_m (dWih[r][m]+dWhh[r][m]) * dWhr[m][j]
// 512 threads, 1 col/thread, 8 rows/block -> 3 blocks/SM, one wave.
__global__ void __launch_bounds__(512) weff_kernel(const float* __restrict__ dwih,
                                                   const float* __restrict__ dwhh,
                                                   const float* __restrict__ whr) {
  __shared__ float wcs[8 * 128];
  const int tid = threadIdx.x;
  const int r0 = blockIdx.x * 8;
  float acc[8];
#pragma unroll
  for (int i = 0; i < 8; i++) acc[i] = 0.0f;

  for (int kb = 0; kb < EMB; kb += 128) {
    __syncthreads();
    for (int idx = tid; idx < 8 * 128; idx += 512) {
      int i = idx >> 7, kk = idx & 127;
      int row = r0 + i; if (row > G4I - 1) row = G4I - 1;
      size_t gidx = (size_t)row * EMB + kb + kk;
      wcs[idx] = dwih[gidx] + dwhh[gidx];
    }
    __syncthreads();
#pragma unroll 4
    for (int kk = 0; kk < 128; kk++) {
      float v = (tid < INP) ? __ldg(whr + (size_t)(kb + kk) * INP + tid) : 0.0f;
#pragma unroll
      for (int i = 0; i < 8; i++) acc[i] += wcs[i * 128 + kk] * v;
    }
  }
  if (tid < INP) {
#pragma unroll
    for (int i = 0; i < 8; i++) {
      int row = r0 + i;
      if (row < G4I) g_weff[(size_t)row * INP + tid] = acc[i];
    }
  }
}

// Persistent encoder (R13-proven, unchanged): fp16 weights (52 rows SMEM + 4 in
// regs), HFMA2 4-accumulator inner loop, fp16 h exchange, packed-flag barrier.
extern __shared__ __half esmh[];
__global__ void __launch_bounds__(256, 1) enc_kernel() {
  __shared__ float gsum[64];
  const int tid = threadIdx.x, wid = tid >> 5, lane = tid & 31, b = blockIdx.x;
  const int cnt   = (b < 124) ? 14 : 13;
  const int start = (b < 124) ? 14 * b : 1736 + 13 * (b - 124);
  const int nrows = 4 * cnt;
  __half* ws  = esmh;                       // CROWS * 2048 halfs
  __half* hs2 = esmh + (size_t)CROWS * EMB; // 2048 halfs (h staging)

  for (int idx = tid; idx < CROWS * EMB; idx += 256) {
    int i = idx >> 11, k = idx & 2047;
    int e = start + (i >> 2), q = i & 3;
    ws[idx] = g_whh_h[((size_t)(q << 11) + e) * EMB + k];
  }
  uint4 wreg[8];
  const int regrow = 48 + wid;
  const bool hasreg = (wid >= 4) && (regrow < nrows);
  if (hasreg) {
    int e = start + (regrow >> 2), q = regrow & 3;
    const uint4* wr = (const uint4*)(g_whh_h + ((size_t)(q << 11) + e) * EMB);
#pragma unroll
    for (int j = 0; j < 8; j++) wreg[j] = __ldcg(wr + lane + 32 * j);
  }
  __syncthreads();

  float c = 0.0f;
  float gx0 = 0.f, gx1 = 0.f, gx2 = 0.f, gx3 = 0.f;
  if (tid < cnt) {
    size_t base = start + tid;
    gx0 = __ldcg(&g_gx[base]);
    gx1 = __ldcg(&g_gx[base + 2048]);
    gx2 = __ldcg(&g_gx[base + 4096]);
    gx3 = __ldcg(&g_gx[base + 6144]);
  }

  for (int t = 0; t < SEQ; t++) {
    ((uint4*)hs2)[tid] = __ldcg(&((const uint4*)g_hhu)[(t & 1) * 256 + tid]);
    __syncthreads();

    float pf0 = 0.f, pf1 = 0.f, pf2 = 0.f, pf3 = 0.f;
    if (tid < cnt && t + 1 < SEQ) {
      size_t base = (size_t)(t + 1) * G4E + start + tid;
      pf0 = __ldcg(&g_gx[base]);
      pf1 = __ldcg(&g_gx[base + 2048]);
      pf2 = __ldcg(&g_gx[base + 4096]);
      pf3 = __ldcg(&g_gx[base + 6144]);
    }

    uint4 hreg[8];
    const uint4* h4 = (const uint4*)hs2;
#pragma unroll
    for (int j = 0; j < 8; j++) hreg[j] = h4[lane + 32 * j];

#pragma unroll 1
    for (int k = 0; k < 6; k++) {      // rows 0..47: all SMEM
      int i = wid + 8 * k;
      const uint4* wr = (const uint4*)(ws + (size_t)i * EMB);
      __half2 a0 = __floats2half2_rn(0.f, 0.f), a1 = a0, a2 = a0, a3 = a0;
#pragma unroll
      for (int j = 0; j < 8; j++) {
        uint4 w = wr[lane + 32 * j];
        a0 = __hfma2(u2h2(w.x), u2h2(hreg[j].x), a0);
        a1 = __hfma2(u2h2(w.y), u2h2(hreg[j].y), a1);
        a2 = __hfma2(u2h2(w.z), u2h2(hreg[j].z), a2);
        a3 = __hfma2(u2h2(w.w), u2h2(hreg[j].w), a3);
      }
      float2 f0 = __half22float2(a0), f1 = __half22float2(a1);
      float2 f2 = __half22float2(a2), f3 = __half22float2(a3);
      float sum = (f0.x + f0.y) + (f1.x + f1.y) + (f2.x + f2.y) + (f3.x + f3.y);
#pragma unroll
      for (int o = 16; o; o >>= 1) sum += __shfl_xor_sync(0xffffffffu, sum, o);
      if (lane == 0) gsum[i] = sum;
    }
    {  // rows 48..55: SMEM for wid<4, registers for wid>=4
      int i = 48 + wid;
      if (i < nrows) {
        __half2 a0 = __floats2half2_rn(0.f, 0.f), a1 = a0, a2 = a0, a3 = a0;
        if (wid < 4) {
          const uint4* wr = (const uint4*)(ws + (size_t)i * EMB);
#pragma unroll
          for (int j = 0; j < 8; j++) {
            uint4 w = wr[lane + 32 * j];
            a0 = __hfma2(u2h2(w.x), u2h2(hreg[j].x), a0);
            a1 = __hfma2(u2h2(w.y), u2h2(hreg[j].y), a1);
            a2 = __hfma2(u2h2(w.z), u2h2(hreg[j].z), a2);
            a3 = __hfma2(u2h2(w.w), u2h2(hreg[j].w), a3);
          }
        } else {
#pragma unroll
          for (int j = 0; j < 8; j++) {
            uint4 w = wreg[j];
            a0 = __hfma2(u2h2(w.x), u2h2(hreg[j].x), a0);
            a1 = __hfma2(u2h2(w.y), u2h2(hreg[j].y), a1);
            a2 = __hfma2(u2h2(w.z), u2h2(hreg[j].z), a2);
            a3 = __hfma2(u2h2(w.w), u2h2(hreg[j].w), a3);
          }
        }
        float2 f0 = __half22float2(a0), f1 = __half22float2(a1);
        float2 f2 = __half22float2(a2), f3 = __half22float2(a3);
        float sum = (f0.x + f0.y) + (f1.x + f1.y) + (f2.x + f2.y) + (f3.x + f3.y);
#pragma unroll
        for (int o = 16; o; o >>= 1) sum += __shfl_xor_sync(0xffffffffu, sum, o);
        if (lane == 0) gsum[i] = sum;
      }
    }
    __syncthreads();

    if (tid < cnt) {
      float gi = gsum[4 * tid + 0] + gx0;
      float gf = gsum[4 * tid + 1] + gx1;
      float gg = gsum[4 * tid + 2] + gx2;
      float go = gsum[4 * tid + 3] + gx3;
      c = sigf(gf) * c + sigf(gi) * tanhf(gg);
      float hnew = sigf(go) * tanhf(c);
      ((__half*)g_hhu)[((t + 1) & 1) * 2048 + start + tid] = __float2half_rn(hnew);
      if (t == SEQ - 1) g_h[start + tid] = hnew;
      __threadfence();
    }
    gx0 = pf0; gx1 = pf1; gx2 = pf2; gx3 = pf3;

    if (t + 1 < SEQ) {
      __syncwarp();
      if (tid == 0)
        ((volatile unsigned*)g_flag_enc4)[(b >> 2) * 32 + (b & 3)] = (unsigned)(t + 1);
      if (tid < 37) {
        poll4(g_flag_enc4 + tid * 8, (unsigned)(t + 1));
        __threadfence();
      }
      __syncthreads();
    }
  }
}

// g0[r] = dec_Wih[r] . h_enc + bih[r] + bhh[r]
__global__ void dec_g0_kernel(const float* __restrict__ dwih,
                              const float* __restrict__ bih,
                              const float* __restrict__ bhh) {
  int wid = threadIdx.x >> 5, lane = threadIdx.x & 31;
  int row = blockIdx.x * 8 + wid;
  if (row >= G4I) return;
  const float4* w = (const float4*)(dwih + (size_t)row * EMB);
  const float4* h = (const float4*)g_h;
  float sum = 0.0f;
  for (int k = lane; k < EMB / 4; k += 32) {
    float4 a = w[k], b = h[k];
    sum += a.x * b.x + a.y * b.y + a.z * b.z + a.w * b.w;
  }
#pragma unroll
  for (int o = 16; o; o >>= 1) sum += __shfl_xor_sync(0xffffffffu, sum, o);
  if (lane == 0) g_g0[row] = sum + bih[row] + bhh[row];
}

// Persistent decoder (R13-proven): 57 CTAs, fp32, packed-flag barrier, warp0 publish.
__global__ void __launch_bounds__(256, 1) dec_kernel(const float* __restrict__ bih,
                                                     const float* __restrict__ bhh,
                                                     float* __restrict__ out) {
  float* ws   = (float*)esmh;        // 36*INP max
  float* hrs  = ws + 36 * INP;       // INP
  float* bs   = hrs + INP;           // 36
  float* gsum = bs + 36;             // 36
  const int tid = threadIdx.x, wid = tid >> 5, lane = tid & 31, b = blockIdx.x;
  const int cnt = (b == 56) ? 9 : 8;
  const int e0 = 8 * b;
  const int nrows = 4 * cnt;

  for (int idx = tid; idx < nrows * INP; idx += 256) {
    int l = idx / INP, k = idx - l * INP;
    int q = l & 3, el = l >> 2;
    ws[l * INP + k] = g_weff[(size_t)(q * INP + e0 + el) * INP + k];
  }
  if (tid < nrows) {
    int q = tid & 3, el = tid >> 2;
    bs[tid] = bih[q * INP + e0 + el] + bhh[q * INP + e0 + el];
  }
  __syncthreads();

  float c = 0.0f;
  for (int t = 0; t < SEQ; t++) {
    if (t > 0) {
      for (int k = tid; k < INP; k += 256) hrs[k] = __ldcg(&g_hraw[(t & 1) * INP + k]);
      __syncthreads();
#pragma unroll 1
      for (int k8 = 0; k8 < 5; k8++) {
        int l = wid + 8 * k8;
        if (l >= nrows) break;  // warp-uniform
        const float* wr = ws + l * INP;
        float sum = 0.0f;
#pragma unroll 5
        for (int k = lane; k < INP; k += 32) sum += wr[k] * hrs[k];
#pragma unroll
        for (int o = 16; o; o >>= 1) sum += __shfl_xor_sync(0xffffffffu, sum, o);
        if (lane == 0) gsum[l] = sum;
      }
      __syncthreads();
    }
    if (tid < cnt) {
      int e = e0 + tid;
      float gi, gf, gg, go;
      if (t == 0) {
        gi = g_g0[e]; gf = g_g0[INP + e]; gg = g_g0[2 * INP + e]; go = g_g0[3 * INP + e];
      } else {
        gi = gsum[4 * tid + 0] + bs[4 * tid + 0];
        gf = gsum[4 * tid + 1] + bs[4 * tid + 1];
        gg = gsum[4 * tid + 2] + bs[4 * tid + 2];
        go = gsum[4 * tid + 3] + bs[4 * tid + 3];
      }
      c = sigf(gf) * c + sigf(gi) * tanhf(gg);
      out[(size_t)(SEQ - 1 - t) * INP + e] = c;
      g_hraw[((t + 1) & 1) * INP + e] = sigf(go) * tanhf(c);
      __threadfence();
    }
    if (t + 1 < SEQ) {
      __syncwarp();
      if (tid == 0)
        ((volatile unsigned*)g_flag_dec4)[(b >> 2) * 32 + (b & 3)] = (unsigned)(t + 1);
      if (tid < 15) {
        poll4(g_flag_dec4 + tid * 8, (unsigned)(t + 1));
        __threadfence();
      }
      __syncthreads();
    }
  }
}

// In-place row softmax over out[4096][457]
__global__ void softmax_kernel(float* __restrict__ out) {
  __shared__ float red[32];
  const int t = blockIdx.x, tid = threadIdx.x, lane = tid & 31, wid = tid >> 5;
  float v = (tid < INP) ? out[(size_t)t * INP + tid] : -1e30f;
  float m = v;
#pragma unroll
  for (int o = 16; o; o >>= 1) m = fmaxf(m, __shfl_xor_sync(0xffffffffu, m, o));
  if (lane == 0) red[wid] = m;
  __syncthreads();
  m = -1e30f;
  for (int i = 0; i < 16; i++) m = fmaxf(m, red[i]);
  __syncthreads();
  float e = (tid < INP) ? expf(v - m) : 0.0f;
  float sum = e;
#pragma unroll
  for (int o = 16; o; o >>= 1) sum += __shfl_xor_sync(0xffffffffu, sum, o);
  if (lane == 0) red[wid] = sum;
  __syncthreads();
  sum = 0.0f;
  for (int i = 0; i < 16; i++) sum += red[i];
  if (tid < INP) out[(size_t)t * INP + tid] = e / sum;
}

extern "C" void kernel_launch(void* const* d_in, const int* in_sizes, int n_in,
                              void* d_out, int out_size) {
  const float* x    = (const float*)d_in[0];
  const float* eWih = (const float*)d_in[1];
  const float* eWhh = (const float*)d_in[2];
  const float* ebih = (const float*)d_in[3];
  const float* ebhh = (const float*)d_in[4];
  const float* dWih = (const float*)d_in[5];
  const float* dWhh = (const float*)d_in[6];
  const float* dbih = (const float*)d_in[7];
  const float* dbhh = (const float*)d_in[8];
  const float* dWhr = (const float*)d_in[9];
  float* out = (float*)d_out;

  const int enc_smem = (CROWS * EMB + EMB) * 2;                 // 217,088 B
  const int dec_smem = (36 * INP + INP + 72) * 4 + 64;          // ~68 KB
  cudaFuncSetAttribute(enc_kernel, cudaFuncAttributeMaxDynamicSharedMemorySize, enc_smem);
  cudaFuncSetAttribute(dec_kernel, cudaFuncAttributeMaxDynamicSharedMemorySize, dec_smem);

  conv_init_kernel<<<16384, 256>>>(eWhh);
  tr_kernel<<<dim3(256, 15), dim3(32, 8)>>>(eWih);
  gx_kernel<<<dim3(32, 256), 256>>>(x, ebih, ebhh);
  enc_kernel<<<NCTA, 256, enc_smem>>>();
  weff_kernel<<<229, 512>>>(dWih, dWhh, dWhr);
  dec_g0_kernel<<<229, 256>>>(dWih, dbih, dbhh);
  dec_kernel<<<DCTA, 256, dec_smem>>>(dbih, dbhh, out);
  softmax_kernel<<<SEQ, 512>>>(out);
}